// round 1
// baseline (speedup 1.0000x reference)
#include <cuda_runtime.h>
#include <cuda_bf16.h>
#include <math.h>

// Shapes (fixed for this problem): N = in_sizes[2], D = 128, C = 64.
#define D 128
#define C 64
#define ROWS_PER_TILE 64
#define THREADS_MAIN 512   // 16 warps, each owns 4 classes
#define LAMBDA_PROTO 0.5f

// -------- device scratch (no allocations allowed) --------
__device__ float g_sums[C * D];   // per-class vector sums of z
__device__ float g_counts[C];     // per-class counts
__device__ float g_z2[C];         // per-class sum of ||z||^2
__device__ float g_ce;            // sum of per-row CE
__device__ int   g_lbl64;         // 1 if labels buffer is int64, 0 if int32

// ---------------------------------------------------------
// init: zero scratch + detect label dtype.
// int64 labels in [0,64) => every odd 32-bit word is 0.
// ---------------------------------------------------------
__global__ void init_kernel(const unsigned int* __restrict__ lab_w, int N) {
    __shared__ int s_nz;
    int t = threadIdx.x;
    if (t == 0) s_nz = 0;
    for (int i = t; i < C * D; i += blockDim.x) g_sums[i] = 0.0f;
    if (t < C) { g_counts[t] = 0.0f; g_z2[t] = 0.0f; }
    if (t == 0) g_ce = 0.0f;
    __syncthreads();
    int limit = (N - 1) / 2;
    if (limit > 1024) limit = 1024;
    if (t < limit) {
        if (lab_w[2 * t + 1] != 0u) s_nz = 1;  // benign race
    }
    __syncthreads();
    if (t == 0) g_lbl64 = (s_nz == 0) ? 1 : 0;
}

// ---------------------------------------------------------
// main: normalize + per-class register-routed segment sums
// ---------------------------------------------------------
__global__ __launch_bounds__(THREADS_MAIN, 2)
void proto_kernel(const float* __restrict__ emb,
                  const unsigned int* __restrict__ lab_w, int N) {
    __shared__ float s_x[ROWS_PER_TILE * D];   // 32 KB raw rows
    __shared__ float s_inv[ROWS_PER_TILE];     // 1/max(||x||, eps)
    __shared__ float s_z2[ROWS_PER_TILE];      // ||z||^2 per row
    __shared__ int   s_lbl[ROWS_PER_TILE];

    const int tid  = threadIdx.x;
    const int wid  = tid >> 5;
    const int lane = tid & 31;
    const int base = wid * 4;            // this warp owns classes [base, base+4)
    const int lbl64 = g_lbl64;

    // per-lane accumulators: 4 classes x 4 dims (dims lane*4 .. lane*4+3)
    float4 a0 = {0,0,0,0}, a1 = a0, a2 = a0, a3 = a0;
    float  c0 = 0, c1 = 0, c2 = 0, c3 = 0;
    float  q0 = 0, q1 = 0, q2 = 0, q3 = 0;

    const int ntiles = (N + ROWS_PER_TILE - 1) / ROWS_PER_TILE;

    for (int tile = blockIdx.x; tile < ntiles; tile += gridDim.x) {
        const int row0  = tile * ROWS_PER_TILE;
        const int nrows = min(ROWS_PER_TILE, N - row0);

        __syncthreads();   // previous iteration's routing reads done

        if (tid < nrows) {
            int idx = lbl64 ? 2 * (row0 + tid) : (row0 + tid);
            s_lbl[tid] = (int)lab_w[idx];
        }
        // coalesced stage of raw rows (float4)
        {
            const float4* g = (const float4*)(emb + (size_t)row0 * D);
            float4* sx4 = (float4*)s_x;
            const int nf4 = nrows * (D / 4);
            for (int i = tid; i < nf4; i += THREADS_MAIN) sx4[i] = g[i];
        }
        __syncthreads();

        // norms: warp w handles rows [w*4, w*4+4)
        #pragma unroll
        for (int rr = 0; rr < 4; ++rr) {
            int r = wid * 4 + rr;
            if (r < nrows) {
                float4 xv = ((const float4*)&s_x[r * D])[lane];
                float s = xv.x*xv.x + xv.y*xv.y + xv.z*xv.z + xv.w*xv.w;
                #pragma unroll
                for (int o = 16; o; o >>= 1) s += __shfl_xor_sync(0xffffffffu, s, o);
                if (lane == 0) {
                    float nrm = sqrtf(s);
                    float inv = 1.0f / fmaxf(nrm, 1e-12f);
                    s_inv[r] = inv;
                    s_z2[r]  = s * inv * inv;
                }
            }
        }
        __syncthreads();

        // routing: each row consumed by exactly one warp -> no atomics
        #pragma unroll 4
        for (int i = 0; i < nrows; ++i) {
            int k = s_lbl[i] - base;
            if ((unsigned)k < 4u) {
                float  inv = s_inv[i];
                float  z2  = s_z2[i];
                float4 xv  = ((const float4*)&s_x[i * D])[lane];
                switch (k) {
                case 0:
                    a0.x = fmaf(xv.x, inv, a0.x); a0.y = fmaf(xv.y, inv, a0.y);
                    a0.z = fmaf(xv.z, inv, a0.z); a0.w = fmaf(xv.w, inv, a0.w);
                    c0 += 1.0f; q0 += z2; break;
                case 1:
                    a1.x = fmaf(xv.x, inv, a1.x); a1.y = fmaf(xv.y, inv, a1.y);
                    a1.z = fmaf(xv.z, inv, a1.z); a1.w = fmaf(xv.w, inv, a1.w);
                    c1 += 1.0f; q1 += z2; break;
                case 2:
                    a2.x = fmaf(xv.x, inv, a2.x); a2.y = fmaf(xv.y, inv, a2.y);
                    a2.z = fmaf(xv.z, inv, a2.z); a2.w = fmaf(xv.w, inv, a2.w);
                    c2 += 1.0f; q2 += z2; break;
                default:
                    a3.x = fmaf(xv.x, inv, a3.x); a3.y = fmaf(xv.y, inv, a3.y);
                    a3.z = fmaf(xv.z, inv, a3.z); a3.w = fmaf(xv.w, inv, a3.w);
                    c3 += 1.0f; q3 += z2; break;
                }
            }
        }
    }

    // flush accumulators (one-shot, small vs. main loop)
    const int dbase = lane * 4;
    atomicAdd(&g_sums[(base + 0) * D + dbase + 0], a0.x);
    atomicAdd(&g_sums[(base + 0) * D + dbase + 1], a0.y);
    atomicAdd(&g_sums[(base + 0) * D + dbase + 2], a0.z);
    atomicAdd(&g_sums[(base + 0) * D + dbase + 3], a0.w);
    atomicAdd(&g_sums[(base + 1) * D + dbase + 0], a1.x);
    atomicAdd(&g_sums[(base + 1) * D + dbase + 1], a1.y);
    atomicAdd(&g_sums[(base + 1) * D + dbase + 2], a1.z);
    atomicAdd(&g_sums[(base + 1) * D + dbase + 3], a1.w);
    atomicAdd(&g_sums[(base + 2) * D + dbase + 0], a2.x);
    atomicAdd(&g_sums[(base + 2) * D + dbase + 1], a2.y);
    atomicAdd(&g_sums[(base + 2) * D + dbase + 2], a2.z);
    atomicAdd(&g_sums[(base + 2) * D + dbase + 3], a2.w);
    atomicAdd(&g_sums[(base + 3) * D + dbase + 0], a3.x);
    atomicAdd(&g_sums[(base + 3) * D + dbase + 1], a3.y);
    atomicAdd(&g_sums[(base + 3) * D + dbase + 2], a3.z);
    atomicAdd(&g_sums[(base + 3) * D + dbase + 3], a3.w);
    if (lane == 0) {
        atomicAdd(&g_counts[base + 0], c0); atomicAdd(&g_z2[base + 0], q0);
        atomicAdd(&g_counts[base + 1], c1); atomicAdd(&g_z2[base + 1], q1);
        atomicAdd(&g_counts[base + 2], c2); atomicAdd(&g_z2[base + 2], q2);
        atomicAdd(&g_counts[base + 3], c3); atomicAdd(&g_z2[base + 3], q3);
    }
}

// ---------------------------------------------------------
// CE: one warp per row (C = 64 => 2 logits per lane)
// ---------------------------------------------------------
__global__ __launch_bounds__(256)
void ce_kernel(const float* __restrict__ logits,
               const unsigned int* __restrict__ lab_w, int N) {
    const int lane   = threadIdx.x & 31;
    const int warp   = (blockIdx.x * blockDim.x + threadIdx.x) >> 5;
    const int nwarps = (gridDim.x * blockDim.x) >> 5;
    const int lbl64  = g_lbl64;

    float acc = 0.0f;
    for (int row = warp; row < N; row += nwarps) {
        const float* lr = logits + (size_t)row * C;
        float v0 = lr[lane];
        float v1 = lr[lane + 32];
        float m = fmaxf(v0, v1);
        #pragma unroll
        for (int o = 16; o; o >>= 1) m = fmaxf(m, __shfl_xor_sync(0xffffffffu, m, o));
        float e = expf(v0 - m) + expf(v1 - m);
        #pragma unroll
        for (int o = 16; o; o >>= 1) e += __shfl_xor_sync(0xffffffffu, e, o);
        float lse = m + logf(e);
        int lbl = (int)lab_w[lbl64 ? 2 * row : row];
        float pick = (lbl >= 32) ? v1 : v0;
        float gval = __shfl_sync(0xffffffffu, pick, lbl & 31);
        if (lane == 0) acc += lse - gval;
    }

    // block reduce (lane-0 partials) then one atomic per block
    __shared__ float red[8];
    int wib = threadIdx.x >> 5;
    if (lane == 0) red[wib] = acc;
    __syncthreads();
    if (threadIdx.x == 0) {
        float s = 0.0f;
        for (int i = 0; i < (int)(blockDim.x >> 5); ++i) s += red[i];
        atomicAdd(&g_ce, s);
    }
}

// ---------------------------------------------------------
// finalize: combine into scalar loss
// ---------------------------------------------------------
__global__ void finalize_kernel(float* __restrict__ out, int N) {
    __shared__ float s_pc[C];
    __shared__ float s_v[C];
    int t = threadIdx.x;
    if (t < C) {
        float cnt = g_counts[t];
        float dot = 0.0f;
        #pragma unroll 4
        for (int d = 0; d < D; ++d) {
            float v = g_sums[t * D + d];
            dot = fmaf(v, v, dot);
        }
        float safe = fmaxf(cnt, 1.0f);
        float musq = dot / (safe * safe);
        float ssd  = g_z2[t] - cnt * musq;
        float pc   = ssd / safe;
        bool valid = (cnt > 1.0f);
        s_pc[t] = valid ? pc : 0.0f;
        s_v[t]  = valid ? 1.0f : 0.0f;
    }
    __syncthreads();
    if (t == 0) {
        float sp = 0.0f, nv = 0.0f;
        for (int c = 0; c < C; ++c) { sp += s_pc[c]; nv += s_v[c]; }
        float proto = sp / fmaxf(nv, 1.0f);
        float ce    = g_ce / (float)N;
        out[0] = (1.0f - LAMBDA_PROTO) * ce + LAMBDA_PROTO * proto;
    }
}

// ---------------------------------------------------------
extern "C" void kernel_launch(void* const* d_in, const int* in_sizes, int n_in,
                              void* d_out, int out_size) {
    const float* emb          = (const float*)d_in[0];
    const float* logits       = (const float*)d_in[1];
    const unsigned int* lab_w = (const unsigned int*)d_in[2];
    int N = in_sizes[2];

    init_kernel<<<1, 1024>>>(lab_w, N);
    proto_kernel<<<296, THREADS_MAIN>>>(emb, lab_w, N);
    ce_kernel<<<1024, 256>>>(logits, lab_w, N);
    finalize_kernel<<<1, 64>>>((float*)d_out, N);
}

// round 2
// speedup vs baseline: 1.1898x; 1.1898x over previous
#include <cuda_runtime.h>
#include <cuda_bf16.h>
#include <math.h>

#define D 128
#define C 64
#define ROWS_PER_TILE 64
#define THREADS_MAIN 512   // 16 warps, each owns 4 classes
#define GRID_MAIN 296      // 2 blocks/SM on 148 SMs (full wave)
#define LAMBDA_PROTO 0.5f

// -------- device scratch --------
__device__ float g_sums[C * D];
__device__ float g_counts[C];
__device__ float g_z2[C];
__device__ float g_ce;
__device__ int   g_lbl64;

// Dynamic smem layout (bytes):
//  s_x   : 2 * 64 * 128 floats = 65536
//  s_inv : 2 * 64 floats       = 512
//  s_z2  : 2 * 64 floats       = 512
//  s_lbl : 2 * 64 ints         = 512
//  s_red : 16 floats           = 64
#define SMEM_BYTES (65536 + 512 + 512 + 512 + 64)

// ---------------------------------------------------------
__global__ void init_kernel(const unsigned int* __restrict__ lab_w, int N) {
    __shared__ int s_nz;
    int t = threadIdx.x;
    if (t == 0) s_nz = 0;
    for (int i = t; i < C * D; i += blockDim.x) g_sums[i] = 0.0f;
    if (t < C) { g_counts[t] = 0.0f; g_z2[t] = 0.0f; }
    if (t == 0) g_ce = 0.0f;
    __syncthreads();
    int limit = (N - 1) / 2;
    if (limit > 1024) limit = 1024;
    if (t < limit) {
        if (lab_w[2 * t + 1] != 0u) s_nz = 1;  // benign race
    }
    __syncthreads();
    if (t == 0) g_lbl64 = (s_nz == 0) ? 1 : 0;
}

// ---------------------------------------------------------
__device__ __forceinline__ void stage_tile_async(
    const float* __restrict__ emb, const unsigned int* __restrict__ lab_w,
    int lbl64, int row0, int nrows,
    float* s_x_buf, int* s_lbl_buf, int tid)
{
    const float4* g = (const float4*)(emb + (size_t)row0 * D);
    unsigned int dstx = (unsigned int)__cvta_generic_to_shared(s_x_buf);
    if (nrows == ROWS_PER_TILE) {
        #pragma unroll
        for (int k = 0; k < 4; ++k) {
            int i = tid + k * THREADS_MAIN;
            asm volatile("cp.async.cg.shared.global [%0], [%1], 16;\n"
                         :: "r"(dstx + i * 16), "l"(g + i));
        }
    } else {
        int nf4 = nrows * (D / 4);
        for (int i = tid; i < nf4; i += THREADS_MAIN) {
            asm volatile("cp.async.cg.shared.global [%0], [%1], 16;\n"
                         :: "r"(dstx + i * 16), "l"(g + i));
        }
    }
    if (tid < nrows) {
        const unsigned int* src = lab_w + (lbl64 ? 2 * (row0 + tid) : (row0 + tid));
        unsigned int dstl = (unsigned int)__cvta_generic_to_shared(s_lbl_buf + tid);
        asm volatile("cp.async.ca.shared.global [%0], [%1], 4;\n"
                     :: "r"(dstl), "l"(src));
    }
}

// ---------------------------------------------------------
// Fused: normalize + per-class register-routed segment sums, then CE.
// ---------------------------------------------------------
__global__ __launch_bounds__(THREADS_MAIN, 2)
void fused_kernel(const float* __restrict__ emb,
                  const float* __restrict__ logits,
                  const unsigned int* __restrict__ lab_w, int N)
{
    extern __shared__ float smem[];
    float* s_x   = smem;                          // [2][64*128]
    float* s_inv = smem + 2 * ROWS_PER_TILE * D;  // [2][64]
    float* s_z2  = s_inv + 2 * ROWS_PER_TILE;     // [2][64]
    int*   s_lbl = (int*)(s_z2 + 2 * ROWS_PER_TILE); // [2][64]
    float* s_red = (float*)(s_lbl + 2 * ROWS_PER_TILE); // [16]

    const int tid  = threadIdx.x;
    const int wid  = tid >> 5;
    const int lane = tid & 31;
    const int base = wid * 4;
    const int lbl64 = g_lbl64;

    float4 a0 = {0,0,0,0}, a1 = a0, a2 = a0, a3 = a0;
    float  c0 = 0, c1 = 0, c2 = 0, c3 = 0;
    float  q0 = 0, q1 = 0, q2 = 0, q3 = 0;

    const int ntiles = (N + ROWS_PER_TILE - 1) / ROWS_PER_TILE;

    // ---- prefetch first tile ----
    int tile = blockIdx.x;
    if (tile < ntiles) {
        int row0 = tile * ROWS_PER_TILE;
        int nrows = min(ROWS_PER_TILE, N - row0);
        stage_tile_async(emb, lab_w, lbl64, row0, nrows, s_x, s_lbl, tid);
    }
    asm volatile("cp.async.commit_group;\n" ::: "memory");

    int parity = 0;
    for (; tile < ntiles; tile += GRID_MAIN) {
        // prefetch next tile into other buffer (processed & synced 1 iter ago)
        int nt = tile + GRID_MAIN;
        if (nt < ntiles) {
            int nrow0 = nt * ROWS_PER_TILE;
            int nnrows = min(ROWS_PER_TILE, N - nrow0);
            stage_tile_async(emb, lab_w, lbl64, nrow0, nnrows,
                             s_x + (parity ^ 1) * ROWS_PER_TILE * D,
                             s_lbl + (parity ^ 1) * ROWS_PER_TILE, tid);
        }
        asm volatile("cp.async.commit_group;\n" ::: "memory");
        // wait for current tile (older group) to land
        asm volatile("cp.async.wait_group 1;\n" ::: "memory");
        __syncthreads();

        const int nrows = min(ROWS_PER_TILE, N - tile * ROWS_PER_TILE);
        float* sx  = s_x   + parity * ROWS_PER_TILE * D;
        float* siv = s_inv + parity * ROWS_PER_TILE;
        float* sz2 = s_z2  + parity * ROWS_PER_TILE;
        int*   slb = s_lbl + parity * ROWS_PER_TILE;

        // norms: warp w handles rows w*4..w*4+3
        #pragma unroll
        for (int rr = 0; rr < 4; ++rr) {
            int r = wid * 4 + rr;
            if (r < nrows) {
                float4 xv = ((const float4*)&sx[r * D])[lane];
                float s = xv.x*xv.x + xv.y*xv.y + xv.z*xv.z + xv.w*xv.w;
                #pragma unroll
                for (int o = 16; o; o >>= 1) s += __shfl_xor_sync(0xffffffffu, s, o);
                if (lane == 0) {
                    float inv = (s > 1e-24f) ? rsqrtf(s) : 1e12f;
                    siv[r] = inv;
                    sz2[r] = s * inv * inv;
                }
            }
        }
        __syncthreads();

        // routing: each row consumed by exactly one warp
        #pragma unroll 4
        for (int i = 0; i < nrows; ++i) {
            int k = slb[i] - base;
            if ((unsigned)k < 4u) {
                float  inv = siv[i];
                float  z2  = sz2[i];
                float4 xv  = ((const float4*)&sx[i * D])[lane];
                switch (k) {
                case 0:
                    a0.x = fmaf(xv.x, inv, a0.x); a0.y = fmaf(xv.y, inv, a0.y);
                    a0.z = fmaf(xv.z, inv, a0.z); a0.w = fmaf(xv.w, inv, a0.w);
                    c0 += 1.0f; q0 += z2; break;
                case 1:
                    a1.x = fmaf(xv.x, inv, a1.x); a1.y = fmaf(xv.y, inv, a1.y);
                    a1.z = fmaf(xv.z, inv, a1.z); a1.w = fmaf(xv.w, inv, a1.w);
                    c1 += 1.0f; q1 += z2; break;
                case 2:
                    a2.x = fmaf(xv.x, inv, a2.x); a2.y = fmaf(xv.y, inv, a2.y);
                    a2.z = fmaf(xv.z, inv, a2.z); a2.w = fmaf(xv.w, inv, a2.w);
                    c2 += 1.0f; q2 += z2; break;
                default:
                    a3.x = fmaf(xv.x, inv, a3.x); a3.y = fmaf(xv.y, inv, a3.y);
                    a3.z = fmaf(xv.z, inv, a3.z); a3.w = fmaf(xv.w, inv, a3.w);
                    c3 += 1.0f; q3 += z2; break;
                }
            }
        }
        __syncthreads();
        parity ^= 1;
    }

    // ---- flush per-class accumulators (one-shot) ----
    const int dbase = lane * 4;
    atomicAdd(&g_sums[(base + 0) * D + dbase + 0], a0.x);
    atomicAdd(&g_sums[(base + 0) * D + dbase + 1], a0.y);
    atomicAdd(&g_sums[(base + 0) * D + dbase + 2], a0.z);
    atomicAdd(&g_sums[(base + 0) * D + dbase + 3], a0.w);
    atomicAdd(&g_sums[(base + 1) * D + dbase + 0], a1.x);
    atomicAdd(&g_sums[(base + 1) * D + dbase + 1], a1.y);
    atomicAdd(&g_sums[(base + 1) * D + dbase + 2], a1.z);
    atomicAdd(&g_sums[(base + 1) * D + dbase + 3], a1.w);
    atomicAdd(&g_sums[(base + 2) * D + dbase + 0], a2.x);
    atomicAdd(&g_sums[(base + 2) * D + dbase + 1], a2.y);
    atomicAdd(&g_sums[(base + 2) * D + dbase + 2], a2.z);
    atomicAdd(&g_sums[(base + 2) * D + dbase + 3], a2.w);
    atomicAdd(&g_sums[(base + 3) * D + dbase + 0], a3.x);
    atomicAdd(&g_sums[(base + 3) * D + dbase + 1], a3.y);
    atomicAdd(&g_sums[(base + 3) * D + dbase + 2], a3.z);
    atomicAdd(&g_sums[(base + 3) * D + dbase + 3], a3.w);
    if (lane == 0) {
        atomicAdd(&g_counts[base + 0], c0); atomicAdd(&g_z2[base + 0], q0);
        atomicAdd(&g_counts[base + 1], c1); atomicAdd(&g_z2[base + 1], q1);
        atomicAdd(&g_counts[base + 2], c2); atomicAdd(&g_z2[base + 2], q2);
        atomicAdd(&g_counts[base + 3], c3); atomicAdd(&g_z2[base + 3], q3);
    }

    // ---------------- CE phase ----------------
    // warp-per-row grid-stride, 2 rows in flight for ILP
    const int gw = blockIdx.x * (THREADS_MAIN / 32) + wid;
    const int nw = GRID_MAIN * (THREADS_MAIN / 32);
    float acc = 0.0f;

    const float2* lg2 = (const float2*)logits;
    for (int row = gw; row < N; row += 2 * nw) {
        int rowB = row + nw;
        bool hasB = rowB < N;
        float2 vA = lg2[(size_t)row * (C / 2) + lane];
        float2 vB = hasB ? lg2[(size_t)rowB * (C / 2) + lane] : make_float2(0.f, 0.f);
        int lblA = (int)lab_w[lbl64 ? 2 * row : row];
        int lblB = hasB ? (int)lab_w[lbl64 ? 2 * rowB : rowB] : 0;

        float mA = fmaxf(vA.x, vA.y);
        float mB = fmaxf(vB.x, vB.y);
        #pragma unroll
        for (int o = 16; o; o >>= 1) {
            mA = fmaxf(mA, __shfl_xor_sync(0xffffffffu, mA, o));
            mB = fmaxf(mB, __shfl_xor_sync(0xffffffffu, mB, o));
        }
        float eA = __expf(vA.x - mA) + __expf(vA.y - mA);
        float eB = __expf(vB.x - mB) + __expf(vB.y - mB);
        #pragma unroll
        for (int o = 16; o; o >>= 1) {
            eA += __shfl_xor_sync(0xffffffffu, eA, o);
            eB += __shfl_xor_sync(0xffffffffu, eB, o);
        }
        float pickA = (lblA & 1) ? vA.y : vA.x;
        float pickB = (lblB & 1) ? vB.y : vB.x;
        float gA = __shfl_sync(0xffffffffu, pickA, lblA >> 1);
        float gB = __shfl_sync(0xffffffffu, pickB, lblB >> 1);
        if (lane == 0) {
            acc += (mA + __logf(eA)) - gA;
            if (hasB) acc += (mB + __logf(eB)) - gB;
        }
    }

    __syncthreads();  // tile-loop smem fully retired before reuse
    if (lane == 0) s_red[wid] = acc;
    __syncthreads();
    if (tid == 0) {
        float s = 0.0f;
        #pragma unroll
        for (int i = 0; i < THREADS_MAIN / 32; ++i) s += s_red[i];
        atomicAdd(&g_ce, s);
    }
}

// ---------------------------------------------------------
__global__ __launch_bounds__(256)
void finalize_kernel(float* __restrict__ out, int N) {
    __shared__ float s_pc[C];
    __shared__ float s_v[C];
    int wid = threadIdx.x >> 5, lane = threadIdx.x & 31;
    for (int c = wid; c < C; c += 8) {
        float4 v = ((const float4*)(g_sums + c * D))[lane];
        float dot = v.x*v.x + v.y*v.y + v.z*v.z + v.w*v.w;
        #pragma unroll
        for (int o = 16; o; o >>= 1) dot += __shfl_xor_sync(0xffffffffu, dot, o);
        if (lane == 0) {
            float cnt  = g_counts[c];
            float safe = fmaxf(cnt, 1.0f);
            float musq = dot / (safe * safe);
            float ssd  = g_z2[c] - cnt * musq;
            bool valid = (cnt > 1.0f);
            s_pc[c] = valid ? (ssd / safe) : 0.0f;
            s_v[c]  = valid ? 1.0f : 0.0f;
        }
    }
    __syncthreads();
    if (threadIdx.x == 0) {
        float sp = 0.0f, nv = 0.0f;
        #pragma unroll
        for (int c = 0; c < C; ++c) { sp += s_pc[c]; nv += s_v[c]; }
        float proto = sp / fmaxf(nv, 1.0f);
        float ce    = g_ce / (float)N;
        out[0] = (1.0f - LAMBDA_PROTO) * ce + LAMBDA_PROTO * proto;
    }
}

// ---------------------------------------------------------
extern "C" void kernel_launch(void* const* d_in, const int* in_sizes, int n_in,
                              void* d_out, int out_size) {
    const float* emb          = (const float*)d_in[0];
    const float* logits       = (const float*)d_in[1];
    const unsigned int* lab_w = (const unsigned int*)d_in[2];
    int N = in_sizes[2];

    cudaFuncSetAttribute(fused_kernel,
                         cudaFuncAttributeMaxDynamicSharedMemorySize, SMEM_BYTES);

    init_kernel<<<1, 1024>>>(lab_w, N);
    fused_kernel<<<GRID_MAIN, THREADS_MAIN, SMEM_BYTES>>>(emb, logits, lab_w, N);
    finalize_kernel<<<1, 256>>>((float*)d_out, N);
}

// round 3
// speedup vs baseline: 1.6620x; 1.3969x over previous
#include <cuda_runtime.h>
#include <cuda_bf16.h>
#include <math.h>

#define D 128
#define C 64
#define ROWS_PER_TILE 64
#define THREADS_MAIN 512   // 16 warps, each owns 4 classes
#define GRID_MAIN 296
#define LAMBDA_PROTO 0.5f

// -------- device scratch --------
__device__ float g_sums[C * D];
__device__ float g_counts[C];
__device__ float g_z2[C];
__device__ float g_ce;
__device__ int   g_lbl64;

// smem: s_x 2*64*128 f = 65536 B ; s_lbl 2*64 i = 512 B ; s_red 16 f = 64 B
#define SMEM_BYTES (65536 + 512 + 64)

// ---------------------------------------------------------
__global__ void init_kernel(const unsigned int* __restrict__ lab_w, int N) {
    __shared__ int s_nz;
    int t = threadIdx.x;
    if (t == 0) s_nz = 0;
    for (int i = t; i < C * D; i += blockDim.x) g_sums[i] = 0.0f;
    if (t < C) { g_counts[t] = 0.0f; g_z2[t] = 0.0f; }
    if (t == 0) g_ce = 0.0f;
    __syncthreads();
    int limit = (N - 1) / 2;
    if (limit > 1024) limit = 1024;
    if (t < limit) {
        if (lab_w[2 * t + 1] != 0u) s_nz = 1;  // benign race
    }
    __syncthreads();
    if (t == 0) g_lbl64 = (s_nz == 0) ? 1 : 0;
}

// ---------------------------------------------------------
__device__ __forceinline__ void stage_tile_async(
    const float* __restrict__ emb, const unsigned int* __restrict__ lab_w,
    int lbl64, int row0, int nrows,
    float* s_x_buf, int* s_lbl_buf, int tid)
{
    const float4* g = (const float4*)(emb + (size_t)row0 * D);
    unsigned int dstx = (unsigned int)__cvta_generic_to_shared(s_x_buf);
    if (nrows == ROWS_PER_TILE) {
        #pragma unroll
        for (int k = 0; k < 4; ++k) {
            int i = tid + k * THREADS_MAIN;
            asm volatile("cp.async.cg.shared.global [%0], [%1], 16;\n"
                         :: "r"(dstx + i * 16), "l"(g + i));
        }
    } else {
        int nf4 = nrows * (D / 4);
        for (int i = tid; i < nf4; i += THREADS_MAIN) {
            asm volatile("cp.async.cg.shared.global [%0], [%1], 16;\n"
                         :: "r"(dstx + i * 16), "l"(g + i));
        }
    }
    if (tid < nrows) {
        const unsigned int* src = lab_w + (lbl64 ? 2 * (row0 + tid) : (row0 + tid));
        unsigned int dstl = (unsigned int)__cvta_generic_to_shared(s_lbl_buf + tid);
        asm volatile("cp.async.ca.shared.global [%0], [%1], 4;\n"
                     :: "r"(dstl), "l"(src));
    }
}

// ---------------------------------------------------------
__global__ __launch_bounds__(THREADS_MAIN, 2)
void fused_kernel(const float* __restrict__ emb,
                  const float* __restrict__ logits,
                  const unsigned int* __restrict__ lab_w, int N)
{
    extern __shared__ float smem[];
    float* s_x   = smem;                                  // [2][64*128]
    int*   s_lbl = (int*)(smem + 2 * ROWS_PER_TILE * D);  // [2][64]
    float* s_red = (float*)(s_lbl + 2 * ROWS_PER_TILE);   // [16]

    const int tid  = threadIdx.x;
    const int wid  = tid >> 5;
    const int lane = tid & 31;
    const int base = wid * 4;          // warp owns classes [base, base+4)
    const int lbl64 = g_lbl64;

    float4 a0 = {0,0,0,0}, a1 = a0, a2 = a0, a3 = a0;
    float  c0 = 0, c1 = 0, c2 = 0, c3 = 0;
    float  q0 = 0, q1 = 0, q2 = 0, q3 = 0;

    const int ntiles = (N + ROWS_PER_TILE - 1) / ROWS_PER_TILE;

    int tile = blockIdx.x;
    if (tile < ntiles) {
        int row0 = tile * ROWS_PER_TILE;
        stage_tile_async(emb, lab_w, lbl64, row0,
                         min(ROWS_PER_TILE, N - row0), s_x, s_lbl, tid);
    }
    asm volatile("cp.async.commit_group;\n" ::: "memory");

    int parity = 0;
    for (; tile < ntiles; tile += GRID_MAIN) {
        int nt = tile + GRID_MAIN;
        if (nt < ntiles) {
            int nrow0 = nt * ROWS_PER_TILE;
            stage_tile_async(emb, lab_w, lbl64, nrow0,
                             min(ROWS_PER_TILE, N - nrow0),
                             s_x + (parity ^ 1) * ROWS_PER_TILE * D,
                             s_lbl + (parity ^ 1) * ROWS_PER_TILE, tid);
        }
        asm volatile("cp.async.commit_group;\n" ::: "memory");
        asm volatile("cp.async.wait_group 1;\n" ::: "memory");
        __syncthreads();

        const int nrows = min(ROWS_PER_TILE, N - tile * ROWS_PER_TILE);
        const float* sx  = s_x   + parity * ROWS_PER_TILE * D;
        const int*   slb = s_lbl + parity * ROWS_PER_TILE;

        // ballot-compacted routing: lane tests rows {lane, lane+32}
        int l0 = slb[lane];
        int l1 = slb[lane + 32];
        unsigned k0 = (unsigned)(l0 - base);
        unsigned k1 = (unsigned)(l1 - base);
        unsigned m0 = __ballot_sync(0xffffffffu, (lane      < nrows) && (k0 < 4u));
        unsigned m1 = __ballot_sync(0xffffffffu, (lane + 32 < nrows) && (k1 < 4u));

        #pragma unroll 1
        for (unsigned mm = m0, half = 0; ; mm = m1, half = 32) {
            for (unsigned m = mm; m; m &= m - 1) {
                int i = (__ffs(m) - 1) + half;
                int k = slb[i] - base;                 // uniform per warp
                float4 xv = ((const float4*)&sx[i * D])[lane];
                float s = xv.x*xv.x + xv.y*xv.y + xv.z*xv.z + xv.w*xv.w;
                #pragma unroll
                for (int o = 16; o; o >>= 1) s += __shfl_xor_sync(0xffffffffu, s, o);
                float inv = rsqrtf(fmaxf(s, 1e-24f));  // == 1/max(||x||,1e-12)
                float z2  = s * inv * inv;
                if (k == 0) {
                    a0.x = fmaf(xv.x, inv, a0.x); a0.y = fmaf(xv.y, inv, a0.y);
                    a0.z = fmaf(xv.z, inv, a0.z); a0.w = fmaf(xv.w, inv, a0.w);
                    c0 += 1.0f; q0 += z2;
                } else if (k == 1) {
                    a1.x = fmaf(xv.x, inv, a1.x); a1.y = fmaf(xv.y, inv, a1.y);
                    a1.z = fmaf(xv.z, inv, a1.z); a1.w = fmaf(xv.w, inv, a1.w);
                    c1 += 1.0f; q1 += z2;
                } else if (k == 2) {
                    a2.x = fmaf(xv.x, inv, a2.x); a2.y = fmaf(xv.y, inv, a2.y);
                    a2.z = fmaf(xv.z, inv, a2.z); a2.w = fmaf(xv.w, inv, a2.w);
                    c2 += 1.0f; q2 += z2;
                } else {
                    a3.x = fmaf(xv.x, inv, a3.x); a3.y = fmaf(xv.y, inv, a3.y);
                    a3.z = fmaf(xv.z, inv, a3.z); a3.w = fmaf(xv.w, inv, a3.w);
                    c3 += 1.0f; q3 += z2;
                }
            }
            if (half) break;
        }
        __syncthreads();
        parity ^= 1;
    }

    // ---- flush per-class accumulators (one-shot) ----
    const int dbase = lane * 4;
    atomicAdd(&g_sums[(base + 0) * D + dbase + 0], a0.x);
    atomicAdd(&g_sums[(base + 0) * D + dbase + 1], a0.y);
    atomicAdd(&g_sums[(base + 0) * D + dbase + 2], a0.z);
    atomicAdd(&g_sums[(base + 0) * D + dbase + 3], a0.w);
    atomicAdd(&g_sums[(base + 1) * D + dbase + 0], a1.x);
    atomicAdd(&g_sums[(base + 1) * D + dbase + 1], a1.y);
    atomicAdd(&g_sums[(base + 1) * D + dbase + 2], a1.z);
    atomicAdd(&g_sums[(base + 1) * D + dbase + 3], a1.w);
    atomicAdd(&g_sums[(base + 2) * D + dbase + 0], a2.x);
    atomicAdd(&g_sums[(base + 2) * D + dbase + 1], a2.y);
    atomicAdd(&g_sums[(base + 2) * D + dbase + 2], a2.z);
    atomicAdd(&g_sums[(base + 2) * D + dbase + 3], a2.w);
    atomicAdd(&g_sums[(base + 3) * D + dbase + 0], a3.x);
    atomicAdd(&g_sums[(base + 3) * D + dbase + 1], a3.y);
    atomicAdd(&g_sums[(base + 3) * D + dbase + 2], a3.z);
    atomicAdd(&g_sums[(base + 3) * D + dbase + 3], a3.w);
    if (lane == 0) {
        atomicAdd(&g_counts[base + 0], c0); atomicAdd(&g_z2[base + 0], q0);
        atomicAdd(&g_counts[base + 1], c1); atomicAdd(&g_z2[base + 1], q1);
        atomicAdd(&g_counts[base + 2], c2); atomicAdd(&g_z2[base + 2], q2);
        atomicAdd(&g_counts[base + 3], c3); atomicAdd(&g_z2[base + 3], q3);
    }

    // ---------------- CE phase (4-row ILP per warp) ----------------
    const int gw = blockIdx.x * (THREADS_MAIN / 32) + wid;
    const int nw = GRID_MAIN * (THREADS_MAIN / 32);
    float acc = 0.0f;

    const float2* lg2 = (const float2*)logits;
    for (int row = gw; row < N; row += 4 * nw) {
        float2 v[4]; int lbl[4]; bool has[4]; int r[4];
        #pragma unroll
        for (int j = 0; j < 4; ++j) {
            r[j] = row + j * nw;
            has[j] = r[j] < N;
            v[j] = has[j] ? lg2[(size_t)r[j] * (C / 2) + lane] : make_float2(0.f, 0.f);
            lbl[j] = has[j] ? (int)lab_w[lbl64 ? 2 * r[j] : r[j]] : 0;
        }
        float m[4], e[4];
        #pragma unroll
        for (int j = 0; j < 4; ++j) m[j] = fmaxf(v[j].x, v[j].y);
        #pragma unroll
        for (int o = 16; o; o >>= 1) {
            #pragma unroll
            for (int j = 0; j < 4; ++j)
                m[j] = fmaxf(m[j], __shfl_xor_sync(0xffffffffu, m[j], o));
        }
        #pragma unroll
        for (int j = 0; j < 4; ++j)
            e[j] = __expf(v[j].x - m[j]) + __expf(v[j].y - m[j]);
        #pragma unroll
        for (int o = 16; o; o >>= 1) {
            #pragma unroll
            for (int j = 0; j < 4; ++j)
                e[j] += __shfl_xor_sync(0xffffffffu, e[j], o);
        }
        #pragma unroll
        for (int j = 0; j < 4; ++j) {
            float pick = (lbl[j] & 1) ? v[j].y : v[j].x;
            float gv = __shfl_sync(0xffffffffu, pick, lbl[j] >> 1);
            if (lane == 0 && has[j]) acc += (m[j] + __logf(e[j])) - gv;
        }
    }

    __syncthreads();
    if (lane == 0) s_red[wid] = acc;
    __syncthreads();
    if (tid == 0) {
        float s = 0.0f;
        #pragma unroll
        for (int i = 0; i < THREADS_MAIN / 32; ++i) s += s_red[i];
        atomicAdd(&g_ce, s);
    }
}

// ---------------------------------------------------------
__global__ __launch_bounds__(256)
void finalize_kernel(float* __restrict__ out, int N) {
    __shared__ float s_pc[C];
    __shared__ float s_v[C];
    int wid = threadIdx.x >> 5, lane = threadIdx.x & 31;
    for (int c = wid; c < C; c += 8) {
        float4 v = ((const float4*)(g_sums + c * D))[lane];
        float dot = v.x*v.x + v.y*v.y + v.z*v.z + v.w*v.w;
        #pragma unroll
        for (int o = 16; o; o >>= 1) dot += __shfl_xor_sync(0xffffffffu, dot, o);
        if (lane == 0) {
            float cnt  = g_counts[c];
            float safe = fmaxf(cnt, 1.0f);
            float musq = dot / (safe * safe);
            float ssd  = g_z2[c] - cnt * musq;
            bool valid = (cnt > 1.0f);
            s_pc[c] = valid ? (ssd / safe) : 0.0f;
            s_v[c]  = valid ? 1.0f : 0.0f;
        }
    }
    __syncthreads();
    if (threadIdx.x == 0) {
        float sp = 0.0f, nv = 0.0f;
        #pragma unroll
        for (int c = 0; c < C; ++c) { sp += s_pc[c]; nv += s_v[c]; }
        float proto = sp / fmaxf(nv, 1.0f);
        float ce    = g_ce / (float)N;
        out[0] = (1.0f - LAMBDA_PROTO) * ce + LAMBDA_PROTO * proto;
    }
}

// ---------------------------------------------------------
extern "C" void kernel_launch(void* const* d_in, const int* in_sizes, int n_in,
                              void* d_out, int out_size) {
    const float* emb          = (const float*)d_in[0];
    const float* logits       = (const float*)d_in[1];
    const unsigned int* lab_w = (const unsigned int*)d_in[2];
    int N = in_sizes[2];

    cudaFuncSetAttribute(fused_kernel,
                         cudaFuncAttributeMaxDynamicSharedMemorySize, SMEM_BYTES);

    init_kernel<<<1, 1024>>>(lab_w, N);
    fused_kernel<<<GRID_MAIN, THREADS_MAIN, SMEM_BYTES>>>(emb, logits, lab_w, N);
    finalize_kernel<<<1, 256>>>((float*)d_out, N);
}